// round 13
// baseline (speedup 1.0000x reference)
#include <cuda_runtime.h>
#include <cstdint>

// ---------------- problem constants ----------------
#define NUM_EXPERTS   64
#define DIM           2048
#define HIDDEN_DIM    1024
#define TOKENS_PER_E  256
#define TOTAL_TOKENS  (NUM_EXPERTS * TOKENS_PER_E)   // 16384

// ---------------- tiling ----------------
// CTA tile 128x128, BK=32. 4 warps in 2x2 grid; warp tile 64x64 (mt=4, nt=8).
#define BM 128
#define BN 128
#define BK 32
#define XS_STRIDE 36    // conflict-free frag LDS + cp.async deposits
#define WS_STRIDE 136   // 136 % 32 == 8 -> conflict-free patterns
#define X_BUF (BM * XS_STRIDE)            // 4608 floats
#define W_BUF (BK * WS_STRIDE)            // 4352 floats
#define STAGE_FLOATS (X_BUF + W_BUF)      // 8960
#define NSTAGE 3
#define SMEM_BYTES (NSTAGE * STAGE_FLOATS * 4)   // 107520 B

// Scratch: t1 = x@w1 (gate pre-activation), h = swiglu output.
__device__ float g_t1[(size_t)TOTAL_TOKENS * HIDDEN_DIM];
__device__ float g_h [(size_t)TOTAL_TOKENS * HIDDEN_DIM];

// ---------------- helpers ----------------

__device__ __forceinline__ uint32_t smem_u32(const void* p) {
    uint32_t a;
    asm("{ .reg .u64 t; cvta.to.shared.u64 t, %1; cvt.u32.u64 %0, t; }" : "=r"(a) : "l"(p));
    return a;
}

__device__ __forceinline__ uint32_t frag_rna(float f) {
    // round-to-nearest tf32 applied on the register fragment (RNA on both
    // operands -> identical numerics to staging-time conversion)
    asm("cvt.rna.tf32.f32 %0, %0;" : "+f"(f));
    return __float_as_uint(f);
}

__device__ __forceinline__ void mma_tf32(float c[4],
                                         const uint32_t a[4],
                                         uint32_t b0, uint32_t b1) {
    asm volatile(
        "mma.sync.aligned.m16n8k8.row.col.f32.tf32.tf32.f32 "
        "{%0,%1,%2,%3}, {%4,%5,%6,%7}, {%8,%9}, {%0,%1,%2,%3};"
        : "+f"(c[0]), "+f"(c[1]), "+f"(c[2]), "+f"(c[3])
        : "r"(a[0]), "r"(a[1]), "r"(a[2]), "r"(a[3]), "r"(b0), "r"(b1));
}

__device__ __forceinline__ float silu(float g) {
    return g / (1.0f + __expf(-g));
}

__device__ __forceinline__ void cp_async16(uint32_t smem_addr, const void* gptr) {
    asm volatile("cp.async.cg.shared.global [%0], [%1], 16;"
                 :: "r"(smem_addr), "l"(gptr) : "memory");
}
#define CP_COMMIT() asm volatile("cp.async.commit_group;" ::: "memory")
#define CP_WAIT1()  asm volatile("cp.async.wait_group 1;" ::: "memory")

// ---------------- GEMM template ----------------
// out = A[tok x KTOT] @ W[e][KTOT x NTOT]; EPI==1: out = silu(gate) * acc

template<int KTOT, int NTOT, int EPI>
__global__ __launch_bounds__(128, 2)
void gemm_kernel(const float* __restrict__ A,
                 const float* __restrict__ W,
                 const float* __restrict__ gate,
                 float* __restrict__ out) {
    extern __shared__ float sm[];
    const uint32_t sb = smem_u32(sm);

    const int e    = blockIdx.z;
    const int mblk = blockIdx.y;
    const int nblk = blockIdx.x;
    const int tid  = threadIdx.x;
    const int lane = tid & 31;
    const int warp = tid >> 5;
    const int wm   = warp >> 1;   // 0..1 (M half)
    const int wn   = warp & 1;    // 0..1 (N half)

    const int tok_base = e * TOKENS_PER_E + mblk * BM;
    const float* Ag = A + (size_t)tok_base * KTOT;
    const float* Wg = W + (size_t)e * KTOT * NTOT + nblk * BN;

    float acc[4][8][4];
#pragma unroll
    for (int mt = 0; mt < 4; mt++)
#pragma unroll
        for (int nt = 0; nt < 8; nt++)
#pragma unroll
            for (int i = 0; i < 4; i++) acc[mt][nt][i] = 0.0f;

    // staging thread coords (128 threads)
    const int sr  = tid >> 3;        // 0..15
    const int sc4 = (tid & 7) * 4;   // 0..28

    // per-thread smem deposit offsets (bytes), fixed per stage slot
    uint32_t x_off[8], w_off[8];
#pragma unroll
    for (int p = 0; p < 8; p++)
        x_off[p] = (uint32_t)(((sr + p * 16) * XS_STRIDE + sc4) * 4);
#pragma unroll
    for (int p = 0; p < 2; p++)
#pragma unroll
        for (int cb = 0; cb < 4; cb++)
            w_off[p * 4 + cb] =
                (uint32_t)((X_BUF + (sr + p * 16) * WS_STRIDE + cb * 32 + sc4) * 4);

    const int NK = KTOT / BK;

    // issue one k-tile into stage slot
    auto issue = [&](int slot, int k0) {
        const uint32_t base = sb + (uint32_t)(slot * STAGE_FLOATS * 4);
#pragma unroll
        for (int p = 0; p < 8; p++)
            cp_async16(base + x_off[p],
                       Ag + (size_t)(sr + p * 16) * KTOT + k0 + sc4);
#pragma unroll
        for (int p = 0; p < 2; p++)
#pragma unroll
            for (int cb = 0; cb < 4; cb++)
                cp_async16(base + w_off[p * 4 + cb],
                           Wg + (size_t)(k0 + sr + p * 16) * NTOT + cb * 32 + sc4);
    };

    // prologue: stages 0 and 1
    issue(0, 0);
    CP_COMMIT();
    if (NK > 1) issue(1, BK);
    CP_COMMIT();

#pragma unroll 1
    for (int i = 0; i < NK; i++) {
        CP_WAIT1();          // stage i landed (<=1 newer group pending)
        __syncthreads();

        // issue stage i+2 (slot reuse is safe: all warps passed compute(i-1))
        if (i + 2 < NK) issue((i + 2) % NSTAGE, (i + 2) * BK);
        CP_COMMIT();         // unconditional: keeps group counting uniform

        const float* Xb = sm + (i % NSTAGE) * STAGE_FLOATS;
        const float* Wb = Xb + X_BUF;
        const int q = lane >> 2;
        const int j = lane & 3;

#pragma unroll
        for (int ks = 0; ks < BK; ks += 8) {
            uint32_t a[4][4];
            const int ac = ks + j;
#pragma unroll
            for (int mt = 0; mt < 4; mt++) {
                const int r = wm * 64 + mt * 16 + q;
                a[mt][0] = frag_rna(Xb[r       * XS_STRIDE + ac]);
                a[mt][1] = frag_rna(Xb[(r + 8) * XS_STRIDE + ac]);
                a[mt][2] = frag_rna(Xb[r       * XS_STRIDE + ac + 4]);
                a[mt][3] = frag_rna(Xb[(r + 8) * XS_STRIDE + ac + 4]);
            }
            const int br = ks + j;
#pragma unroll
            for (int nt = 0; nt < 8; nt++) {
                const int bc = wn * 64 + nt * 8 + q;
                const uint32_t b0 = frag_rna(Wb[br       * WS_STRIDE + bc]);
                const uint32_t b1 = frag_rna(Wb[(br + 4) * WS_STRIDE + bc]);
#pragma unroll
                for (int mt = 0; mt < 4; mt++)
                    mma_tf32(acc[mt][nt], a[mt], b0, b1);
            }
        }
        __syncthreads();     // all warps done with slot i before it is refilled
    }

    // ---- epilogue ----
    const int q = lane >> 2;
    const int j = lane & 3;
#pragma unroll
    for (int mt = 0; mt < 4; mt++) {
#pragma unroll
        for (int h = 0; h < 2; h++) {
            const int row = tok_base + wm * 64 + mt * 16 + q + h * 8;
#pragma unroll
            for (int nt = 0; nt < 8; nt++) {
                const int col = nblk * BN + wn * 64 + nt * 8 + j * 2;
                float v0 = acc[mt][nt][h * 2 + 0];
                float v1 = acc[mt][nt][h * 2 + 1];
                if (EPI == 1) {
                    float2 g = *reinterpret_cast<const float2*>(
                        gate + (size_t)row * NTOT + col);
                    v0 = silu(g.x) * v0;
                    v1 = silu(g.y) * v1;
                }
                *reinterpret_cast<float2*>(out + (size_t)row * NTOT + col) =
                    make_float2(v0, v1);
            }
        }
    }
}

// ---------------- launch ----------------

extern "C" void kernel_launch(void* const* d_in, const int* in_sizes, int n_in,
                              void* d_out, int out_size) {
    const float* x  = (const float*)d_in[0];
    const float* w1 = (const float*)d_in[1];
    const float* w2 = (const float*)d_in[2];
    const float* w3 = (const float*)d_in[3];
    float* out = (float*)d_out;

    float *t1, *h;
    cudaGetSymbolAddress((void**)&t1, g_t1);   // host-side query, capture-safe
    cudaGetSymbolAddress((void**)&h,  g_h);

    cudaFuncSetAttribute(gemm_kernel<DIM, HIDDEN_DIM, 0>,
                         cudaFuncAttributeMaxDynamicSharedMemorySize, SMEM_BYTES);
    cudaFuncSetAttribute(gemm_kernel<DIM, HIDDEN_DIM, 1>,
                         cudaFuncAttributeMaxDynamicSharedMemorySize, SMEM_BYTES);
    cudaFuncSetAttribute(gemm_kernel<HIDDEN_DIM, DIM, 0>,
                         cudaFuncAttributeMaxDynamicSharedMemorySize, SMEM_BYTES);

    dim3 blk(128);
    dim3 grid_up(HIDDEN_DIM / BN, TOKENS_PER_E / BM, NUM_EXPERTS);   // (8, 2, 64)
    dim3 grid_dn(DIM / BN,        TOKENS_PER_E / BM, NUM_EXPERTS);   // (16, 2, 64)

    // U1: t1 = x @ w1
    gemm_kernel<DIM, HIDDEN_DIM, 0><<<grid_up, blk, SMEM_BYTES>>>(x, w1, nullptr, t1);
    // U2: h = silu(t1) * (x @ w3)
    gemm_kernel<DIM, HIDDEN_DIM, 1><<<grid_up, blk, SMEM_BYTES>>>(x, w3, t1, h);
    // D:  out = h @ w2
    gemm_kernel<HIDDEN_DIM, DIM, 0><<<grid_dn, blk, SMEM_BYTES>>>(h, w2, nullptr, out);
}

// round 16
// speedup vs baseline: 1.0194x; 1.0194x over previous
#include <cuda_runtime.h>
#include <cstdint>

// ---------------- problem constants ----------------
#define NUM_EXPERTS   64
#define DIM           2048
#define HIDDEN_DIM    1024
#define TOKENS_PER_E  256
#define TOTAL_TOKENS  (NUM_EXPERTS * TOKENS_PER_E)   // 16384

// ---------------- tiling ----------------
// CTA tile 128x128, BK=32. 4 warps in 2x2 grid; warp tile 64x64 (mt=4, nt=8).
#define BM 128
#define BN 128
#define BK 32
#define XS_STRIDE 36    // conflict-free frag LDS + cp.async deposits
#define WS_STRIDE 136   // 136 % 32 == 8 -> conflict-free patterns
#define X_BUF (BM * XS_STRIDE)            // 4608 floats
#define W_BUF (BK * WS_STRIDE)            // 4352 floats
#define STAGE_FLOATS (X_BUF + W_BUF)      // 8960
#define NSTAGE 2
#define SMEM_BYTES (NSTAGE * STAGE_FLOATS * 4)   // 71680 B -> 3 CTAs/SM = 215KB

// Scratch: t1 = x@w1 (gate pre-activation), h = swiglu output.
__device__ float g_t1[(size_t)TOTAL_TOKENS * HIDDEN_DIM];
__device__ float g_h [(size_t)TOTAL_TOKENS * HIDDEN_DIM];

// ---------------- helpers ----------------

__device__ __forceinline__ uint32_t smem_u32(const void* p) {
    uint32_t a;
    asm("{ .reg .u64 t; cvta.to.shared.u64 t, %1; cvt.u32.u64 %0, t; }" : "=r"(a) : "l"(p));
    return a;
}

__device__ __forceinline__ uint32_t frag_rna(float f) {
    // round-to-nearest tf32 on the register fragment (RNA on both operands ->
    // numerics identical to all prior passing rounds)
    asm("cvt.rna.tf32.f32 %0, %0;" : "+f"(f));
    return __float_as_uint(f);
}

__device__ __forceinline__ void mma_tf32(float c[4],
                                         const uint32_t a[4],
                                         uint32_t b0, uint32_t b1) {
    asm volatile(
        "mma.sync.aligned.m16n8k8.row.col.f32.tf32.tf32.f32 "
        "{%0,%1,%2,%3}, {%4,%5,%6,%7}, {%8,%9}, {%0,%1,%2,%3};"
        : "+f"(c[0]), "+f"(c[1]), "+f"(c[2]), "+f"(c[3])
        : "r"(a[0]), "r"(a[1]), "r"(a[2]), "r"(a[3]), "r"(b0), "r"(b1));
}

__device__ __forceinline__ float silu(float g) {
    return g / (1.0f + __expf(-g));
}

__device__ __forceinline__ void cp_async16(uint32_t smem_addr, const void* gptr) {
    asm volatile("cp.async.cg.shared.global [%0], [%1], 16;"
                 :: "r"(smem_addr), "l"(gptr) : "memory");
}
#define CP_COMMIT() asm volatile("cp.async.commit_group;" ::: "memory")
#define CP_WAIT1()  asm volatile("cp.async.wait_group 1;" ::: "memory")

// ---------------- GEMM template ----------------
// out = A[tok x KTOT] @ W[e][KTOT x NTOT]; EPI==1: out = silu(gate) * acc
// __launch_bounds__(128, 3): cap regs at 170 -> 3 CTAs/SM (12 warps).

template<int KTOT, int NTOT, int EPI>
__global__ __launch_bounds__(128, 3)
void gemm_kernel(const float* __restrict__ A,
                 const float* __restrict__ W,
                 const float* __restrict__ gate,
                 float* __restrict__ out) {
    extern __shared__ float sm[];
    const uint32_t sb = smem_u32(sm);

    const int e    = blockIdx.z;
    const int mblk = blockIdx.y;
    const int nblk = blockIdx.x;
    const int tid  = threadIdx.x;
    const int lane = tid & 31;
    const int warp = tid >> 5;
    const int wm   = warp >> 1;   // 0..1 (M half)
    const int wn   = warp & 1;    // 0..1 (N half)

    const int tok_base = e * TOKENS_PER_E + mblk * BM;
    const float* Ag = A + (size_t)tok_base * KTOT;
    const float* Wg = W + (size_t)e * KTOT * NTOT + nblk * BN;

    float acc[4][8][4];
#pragma unroll
    for (int mt = 0; mt < 4; mt++)
#pragma unroll
        for (int nt = 0; nt < 8; nt++)
#pragma unroll
            for (int i = 0; i < 4; i++) acc[mt][nt][i] = 0.0f;

    // staging thread coords (128 threads)
    const int sr  = tid >> 3;        // 0..15
    const int sc4 = (tid & 7) * 4;   // 0..28

    const int NK = KTOT / BK;

    // issue one k-tile into a stage slot (offsets computed inline — no
    // persistent offset arrays, keeps register count under the 3-CTA cap)
    auto issue = [&](int slot, int k0) {
        const uint32_t base = sb + (uint32_t)(slot * STAGE_FLOATS * 4);
#pragma unroll
        for (int p = 0; p < 8; p++)
            cp_async16(base + (uint32_t)(((sr + p * 16) * XS_STRIDE + sc4) * 4),
                       Ag + (size_t)(sr + p * 16) * KTOT + k0 + sc4);
#pragma unroll
        for (int p = 0; p < 2; p++)
#pragma unroll
            for (int cb = 0; cb < 4; cb++)
                cp_async16(base + (uint32_t)((X_BUF + (sr + p * 16) * WS_STRIDE
                                              + cb * 32 + sc4) * 4),
                           Wg + (size_t)(k0 + sr + p * 16) * NTOT + cb * 32 + sc4);
    };

    // prologue: stage 0 in flight
    issue(0, 0);
    CP_COMMIT();

    const int q = lane >> 2;
    const int j = lane & 3;

#pragma unroll 1
    for (int i = 0; i < NK; i++) {
        // issue stage i+1 into slot (i+1)&1 — that slot was consumed at i-1,
        // and the end-of-iteration barrier makes reuse safe.
        if (i + 1 < NK) issue((i + 1) & 1, (i + 1) * BK);
        CP_COMMIT();          // unconditional: uniform group counting
        CP_WAIT1();           // stage i landed (only stage i+1 still pending)
        __syncthreads();

        const float* Xb = sm + (i & 1) * STAGE_FLOATS;
        const float* Wb = Xb + X_BUF;

#pragma unroll
        for (int ks = 0; ks < BK; ks += 8) {
            uint32_t a[4][4];
            const int ac = ks + j;
#pragma unroll
            for (int mt = 0; mt < 4; mt++) {
                const int r = wm * 64 + mt * 16 + q;
                a[mt][0] = frag_rna(Xb[r       * XS_STRIDE + ac]);
                a[mt][1] = frag_rna(Xb[(r + 8) * XS_STRIDE + ac]);
                a[mt][2] = frag_rna(Xb[r       * XS_STRIDE + ac + 4]);
                a[mt][3] = frag_rna(Xb[(r + 8) * XS_STRIDE + ac + 4]);
            }
            const int br = ks + j;
#pragma unroll
            for (int nt = 0; nt < 8; nt++) {
                const int bc = wn * 64 + nt * 8 + q;
                const uint32_t b0 = frag_rna(Wb[br       * WS_STRIDE + bc]);
                const uint32_t b1 = frag_rna(Wb[(br + 4) * WS_STRIDE + bc]);
#pragma unroll
                for (int mt = 0; mt < 4; mt++)
                    mma_tf32(acc[mt][nt], a[mt], b0, b1);
            }
        }
        __syncthreads();      // all warps done with slot i before refill at i+1
    }

    // ---- epilogue ----
#pragma unroll
    for (int mt = 0; mt < 4; mt++) {
#pragma unroll
        for (int h = 0; h < 2; h++) {
            const int row = tok_base + wm * 64 + mt * 16 + q + h * 8;
#pragma unroll
            for (int nt = 0; nt < 8; nt++) {
                const int col = nblk * BN + wn * 64 + nt * 8 + j * 2;
                float v0 = acc[mt][nt][h * 2 + 0];
                float v1 = acc[mt][nt][h * 2 + 1];
                if (EPI == 1) {
                    float2 g = *reinterpret_cast<const float2*>(
                        gate + (size_t)row * NTOT + col);
                    v0 = silu(g.x) * v0;
                    v1 = silu(g.y) * v1;
                }
                *reinterpret_cast<float2*>(out + (size_t)row * NTOT + col) =
                    make_float2(v0, v1);
            }
        }
    }
}

// ---------------- launch ----------------

extern "C" void kernel_launch(void* const* d_in, const int* in_sizes, int n_in,
                              void* d_out, int out_size) {
    const float* x  = (const float*)d_in[0];
    const float* w1 = (const float*)d_in[1];
    const float* w2 = (const float*)d_in[2];
    const float* w3 = (const float*)d_in[3];
    float* out = (float*)d_out;

    float *t1, *h;
    cudaGetSymbolAddress((void**)&t1, g_t1);   // host-side query, capture-safe
    cudaGetSymbolAddress((void**)&h,  g_h);

    cudaFuncSetAttribute(gemm_kernel<DIM, HIDDEN_DIM, 0>,
                         cudaFuncAttributeMaxDynamicSharedMemorySize, SMEM_BYTES);
    cudaFuncSetAttribute(gemm_kernel<DIM, HIDDEN_DIM, 1>,
                         cudaFuncAttributeMaxDynamicSharedMemorySize, SMEM_BYTES);
    cudaFuncSetAttribute(gemm_kernel<HIDDEN_DIM, DIM, 0>,
                         cudaFuncAttributeMaxDynamicSharedMemorySize, SMEM_BYTES);

    dim3 blk(128);
    dim3 grid_up(HIDDEN_DIM / BN, TOKENS_PER_E / BM, NUM_EXPERTS);   // (8, 2, 64)
    dim3 grid_dn(DIM / BN,        TOKENS_PER_E / BM, NUM_EXPERTS);   // (16, 2, 64)

    // U1: t1 = x @ w1
    gemm_kernel<DIM, HIDDEN_DIM, 0><<<grid_up, blk, SMEM_BYTES>>>(x, w1, nullptr, t1);
    // U2: h = silu(t1) * (x @ w3)
    gemm_kernel<DIM, HIDDEN_DIM, 1><<<grid_up, blk, SMEM_BYTES>>>(x, w3, t1, h);
    // D:  out = h @ w2
    gemm_kernel<HIDDEN_DIM, DIM, 0><<<grid_dn, blk, SMEM_BYTES>>>(h, w2, nullptr, out);
}